// round 4
// baseline (speedup 1.0000x reference)
#include <cuda_runtime.h>
#include <cuda_fp16.h>
#include <cstdint>

#define USER_NUM 100000
#define ITEM_NUM 100000
#define N_NODES  (USER_NUM + ITEM_NUM)   // 200000
#define EMB      64
#define EMB2     (EMB / 2)               // 32 half2 per row
#define NNZ      4000000
#define CAP      64                      // bucket capacity per row (deg~Poisson(20))

// ---------------- scratch (allocation-free: __device__ globals) ----------------
__device__ int    g_cnt[N_NODES];                      // per-row edge count
__device__ int2   g_bucket[(size_t)N_NODES * CAP];     // {col, val bits} per row
__device__ __half g_b0[(size_t)N_NODES * EMB];         // ego0
__device__ __half g_b1[(size_t)N_NODES * EMB];         // layer1 out
__device__ __half g_b2[(size_t)N_NODES * EMB];         // layer2 out
__device__ int    g_is64;                              // 1 if adj indices are int64

// ---------------- zero counts + fused dtype detection ----------------
// int64 indices (< 2^31): every odd 32-bit word is 0. int32: random indices.
__global__ void k_zero_detect(const unsigned int* __restrict__ rowraw) {
    int i = blockIdx.x * blockDim.x + threadIdx.x;
    if (i < N_NODES) g_cnt[i] = 0;
    if (blockIdx.x == 0 && threadIdx.x == 0) {
        unsigned int acc = 0;
        #pragma unroll
        for (int j = 1; j < 128; j += 2) acc |= rowraw[j];
        g_is64 = (acc == 0u) ? 1 : 0;
    }
}

__device__ __forceinline__ int load_idx(const void* __restrict__ p, int e, int is64) {
    if (is64) return (int)((const long long*)p)[e];
    return ((const int*)p)[e];
}

// ---------------- single-pass bucketed scatter ----------------
__global__ void k_scatter(const void* __restrict__ row,
                          const void* __restrict__ col,
                          const float* __restrict__ val) {
    int e = blockIdx.x * blockDim.x + threadIdx.x;
    int is64 = g_is64;
    if (e < NNZ) {
        int r = load_idx(row, e, is64);
        int p = atomicAdd(&g_cnt[r], 1);
        if (p < CAP) {
            int2 ed;
            ed.x = load_idx(col, e, is64);
            ed.y = __float_as_int(val[e]);
            g_bucket[(size_t)r * CAP + p] = ed;
        }
    }
}

// ---------------- ego init (fp32 -> fp16) ----------------
__global__ void k_init(const float* __restrict__ user,
                       const float* __restrict__ item) {
    size_t i = (size_t)blockIdx.x * blockDim.x + threadIdx.x;
    if (i < (size_t)N_NODES * EMB) {
        float v = (i < (size_t)USER_NUM * EMB) ? user[i]
                                               : item[i - (size_t)USER_NUM * EMB];
        g_b0[i] = __float2half(v);
    }
}

// ---------------- SpMM (fp16 in, fp32 accumulate) ----------------
// One warp per row; lane owns 2 embedding cols (one half2).
__device__ __forceinline__ float2 spmm_row(const __half2* __restrict__ x,
                                           int row, int lane) {
    int deg = g_cnt[row];
    if (deg > CAP) deg = CAP;
    const int2* __restrict__ ep = g_bucket + (size_t)row * CAP;
    float a0 = 0.0f, a1 = 0.0f;
    #pragma unroll 8
    for (int k = 0; k < deg; k++) {
        int2 ed = __ldg(&ep[k]);
        float v = __int_as_float(ed.y);
        __half2 xh = __ldg(&x[(size_t)ed.x * EMB2 + lane]);
        float2 xv = __half22float2(xh);
        a0 = fmaf(v, xv.x, a0);
        a1 = fmaf(v, xv.y, a1);
    }
    float2 r; r.x = a0; r.y = a1;
    return r;
}

__global__ void __launch_bounds__(256)
k_spmm_mid(const __half2* __restrict__ x, __half2* __restrict__ y) {
    int row  = (blockIdx.x * blockDim.x + threadIdx.x) >> 5;
    int lane = threadIdx.x & 31;
    if (row >= N_NODES) return;
    float2 r = spmm_row(x, row, lane);
    y[(size_t)row * EMB2 + lane] = __floats2half2_rn(r.x, r.y);
}

// Layer 3: fuse the (e1 + e2 + e3)/3 reduction, write fp32 output directly.
__global__ void __launch_bounds__(256)
k_spmm_last(const __half2* __restrict__ x,      // = e2 (gather source)
            const __half2* __restrict__ e1,
            float* __restrict__ out) {
    int row  = (blockIdx.x * blockDim.x + threadIdx.x) >> 5;
    int lane = threadIdx.x & 31;
    if (row >= N_NODES) return;
    float2 r = spmm_row(x, row, lane);
    size_t o = (size_t)row * EMB2 + lane;
    float2 v1 = __half22float2(e1[o]);
    float2 v2 = __half22float2(x[o]);
    float2 acc;
    acc.x = (v1.x + v2.x + r.x) * (1.0f / 3.0f);
    acc.y = (v1.y + v2.y + r.y) * (1.0f / 3.0f);
    *reinterpret_cast<float2*>(out + (size_t)row * EMB + lane * 2) = acc;
}

extern "C" void kernel_launch(void* const* d_in, const int* in_sizes, int n_in,
                              void* d_out, int out_size) {
    const float* user = (const float*)d_in[0];
    const float* item = (const float*)d_in[1];
    const void*  arow = d_in[2];
    const void*  acol = d_in[3];
    const float* aval = (const float*)d_in[4];
    float* out = (float*)d_out;

    __half2 *b0, *b1, *b2;
    cudaGetSymbolAddress((void**)&b0, g_b0);
    cudaGetSymbolAddress((void**)&b1, g_b1);
    cudaGetSymbolAddress((void**)&b2, g_b2);

    const int T = 256;
    const int nodeBlocks = (N_NODES + T - 1) / T;
    const int edgeBlocks = (NNZ + T - 1) / T;
    const int embBlocks  = (int)(((size_t)N_NODES * EMB + T - 1) / T);
    const int spmmBlocks = (N_NODES * 32 + T - 1) / T;

    // ---- single-pass bucketed build ----
    k_zero_detect<<<nodeBlocks, T>>>((const unsigned int*)arow);
    k_scatter<<<edgeBlocks, T>>>(arow, acol, aval);

    // ---- init ego (fp16) ----
    k_init<<<embBlocks, T>>>(user, item);

    // ---- 3 propagation layers; layer 3 fuses the mean reduction ----
    k_spmm_mid <<<spmmBlocks, T>>>(b0, b1);        // e1 = A @ ego0
    k_spmm_mid <<<spmmBlocks, T>>>(b1, b2);        // e2 = A @ e1
    k_spmm_last<<<spmmBlocks, T>>>(b2, b1, out);   // out = (e1+e2+A@e2)/3
}

// round 6
// speedup vs baseline: 1.5557x; 1.5557x over previous
#include <cuda_runtime.h>
#include <cuda_fp16.h>
#include <cstdint>

#define USER_NUM 100000
#define ITEM_NUM 100000
#define N_NODES  (USER_NUM + ITEM_NUM)   // 200000
#define EMB      64
#define ROWU4    8                       // 8 uint4 (16B) per row = 128B
#define NNZ      4000000
#define SCAN_CHUNK 1024
#define NUM_CHUNKS ((N_NODES + SCAN_CHUNK - 1) / SCAN_CHUNK)   // 196

// ---------------- scratch (allocation-free: __device__ globals) ----------------
__device__ int    g_rowptr[N_NODES + 1];
__device__ int    g_cursor[N_NODES];          // histogram counts, then scatter cursors
__device__ int    g_bsum[NUM_CHUNKS];
__device__ int    g_bsum2[NUM_CHUNKS];
__device__ int2   g_edge[NNZ];                // compact {col, val bits}
__device__ __half g_b0[(size_t)N_NODES * EMB];
__device__ __half g_b1[(size_t)N_NODES * EMB];
__device__ __half g_b2[(size_t)N_NODES * EMB];
__device__ int    g_is64;

// ---------------- zero counts + fused dtype detection ----------------
// int64 indices (< 2^31): every odd 32-bit word is 0. int32: random node ids.
__global__ void k_zero_detect(const unsigned int* __restrict__ rowraw) {
    int i = blockIdx.x * blockDim.x + threadIdx.x;
    if (i < N_NODES) g_cursor[i] = 0;
    if (blockIdx.x == 0 && threadIdx.x == 0) {
        unsigned int acc = 0;
        #pragma unroll
        for (int j = 1; j < 128; j += 2) acc |= rowraw[j];
        g_is64 = (acc == 0u) ? 1 : 0;
    }
}

__device__ __forceinline__ int load_idx(const void* __restrict__ p, int e, int is64) {
    if (is64) return (int)((const long long*)p)[e];
    return ((const int*)p)[e];
}

// ---------------- CSR build (two-pass, compact) ----------------
__global__ void k_hist(const void* __restrict__ row) {
    int e = blockIdx.x * blockDim.x + threadIdx.x;
    int is64 = g_is64;
    if (e < NNZ) atomicAdd(&g_cursor[load_idx(row, e, is64)], 1);
}

__global__ void k_scan_chunks() {
    __shared__ int s[SCAN_CHUNK];
    int base = blockIdx.x * SCAN_CHUNK;
    int tid  = threadIdx.x;
    int i    = base + tid;
    int v    = (i < N_NODES) ? g_cursor[i] : 0;
    s[tid] = v;
    __syncthreads();
    #pragma unroll
    for (int off = 1; off < SCAN_CHUNK; off <<= 1) {
        int t = (tid >= off) ? s[tid - off] : 0;
        __syncthreads();
        s[tid] += t;
        __syncthreads();
    }
    int incl = s[tid];
    if (i < N_NODES) g_rowptr[i] = incl - v;       // exclusive
    if (tid == SCAN_CHUNK - 1) g_bsum[blockIdx.x] = incl;
}

__global__ void k_scan_bsum() {
    __shared__ int s[256];
    int tid = threadIdx.x;
    int v = (tid < NUM_CHUNKS) ? g_bsum[tid] : 0;
    s[tid] = v;
    __syncthreads();
    #pragma unroll
    for (int off = 1; off < 256; off <<= 1) {
        int t = (tid >= off) ? s[tid - off] : 0;
        __syncthreads();
        s[tid] += t;
        __syncthreads();
    }
    if (tid < NUM_CHUNKS) g_bsum2[tid] = s[tid] - v;
}

__global__ void k_finalize_ptr() {
    int i = blockIdx.x * blockDim.x + threadIdx.x;
    if (i < N_NODES) {
        int v = g_rowptr[i] + g_bsum2[i / SCAN_CHUNK];
        g_rowptr[i] = v;
        g_cursor[i] = v;
        if (i == 0) g_rowptr[N_NODES] = NNZ;
    }
}

__global__ void k_scatter(const void* __restrict__ row,
                          const void* __restrict__ col,
                          const float* __restrict__ val) {
    int e = blockIdx.x * blockDim.x + threadIdx.x;
    int is64 = g_is64;
    if (e < NNZ) {
        int r = load_idx(row, e, is64);
        int p = atomicAdd(&g_cursor[r], 1);
        int2 ed;
        ed.x = load_idx(col, e, is64);
        ed.y = __float_as_int(val[e]);
        g_edge[p] = ed;
    }
}

// ---------------- ego init (fp32 -> fp16) ----------------
__global__ void k_init(const float* __restrict__ user,
                       const float* __restrict__ item) {
    size_t i = (size_t)blockIdx.x * blockDim.x + threadIdx.x;
    if (i < (size_t)N_NODES * EMB) {
        float v = (i < (size_t)USER_NUM * EMB) ? user[i]
                                               : item[i - (size_t)USER_NUM * EMB];
        g_b0[i] = __float2half(v);
    }
}

// ---------------- SpMM: 8 lanes per row, LDG.128 gathers ----------------
__device__ __forceinline__ void fma_h2(float& a0, float& a1, float v, unsigned int bits) {
    __half2 h = *reinterpret_cast<const __half2*>(&bits);
    float2 f = __half22float2(h);
    a0 = fmaf(v, f.x, a0);
    a1 = fmaf(v, f.y, a1);
}

// Accumulate this (row, sub) slice: 8 floats (4 half2 = 16B of the 128B row).
__device__ __forceinline__ void spmm_slice(const uint4* __restrict__ x,
                                           int row, int sub, float* a) {
    int s = g_rowptr[row];
    int e = g_rowptr[row + 1];
    #pragma unroll 4
    for (int k = s; k < e; k++) {
        int2 ed = __ldg(&g_edge[k]);
        float v = __int_as_float(ed.y);
        uint4 q = __ldg(&x[(size_t)ed.x * ROWU4 + sub]);
        fma_h2(a[0], a[1], v, q.x);
        fma_h2(a[2], a[3], v, q.y);
        fma_h2(a[4], a[5], v, q.z);
        fma_h2(a[6], a[7], v, q.w);
    }
}

__device__ __forceinline__ unsigned int pack_h2(float lo, float hi) {
    __half2 h = __floats2half2_rn(lo, hi);
    return *reinterpret_cast<unsigned int*>(&h);
}

__global__ void __launch_bounds__(256)
k_spmm_mid(const uint4* __restrict__ x, uint4* __restrict__ y) {
    int t   = blockIdx.x * blockDim.x + threadIdx.x;
    int row = t >> 3;
    int sub = t & 7;
    if (row >= N_NODES) return;
    float a[8] = {0, 0, 0, 0, 0, 0, 0, 0};
    spmm_slice(x, row, sub, a);
    uint4 o;
    o.x = pack_h2(a[0], a[1]);
    o.y = pack_h2(a[2], a[3]);
    o.z = pack_h2(a[4], a[5]);
    o.w = pack_h2(a[6], a[7]);
    y[(size_t)row * ROWU4 + sub] = o;
}

// Layer 3: fuse the (e1 + e2 + e3)/3 reduction, write fp32 output directly.
__global__ void __launch_bounds__(256)
k_spmm_last(const uint4* __restrict__ x,      // = e2 (gather source)
            const uint4* __restrict__ e1,
            float* __restrict__ out) {
    int t   = blockIdx.x * blockDim.x + threadIdx.x;
    int row = t >> 3;
    int sub = t & 7;
    if (row >= N_NODES) return;
    float a[8] = {0, 0, 0, 0, 0, 0, 0, 0};
    spmm_slice(x, row, sub, a);

    uint4 q1 = e1[(size_t)row * ROWU4 + sub];
    uint4 q2 = x [(size_t)row * ROWU4 + sub];
    const unsigned int* p1 = &q1.x;
    const unsigned int* p2 = &q2.x;
    float r[8];
    #pragma unroll
    for (int j = 0; j < 4; j++) {
        float2 f1 = __half22float2(*reinterpret_cast<const __half2*>(&p1[j]));
        float2 f2 = __half22float2(*reinterpret_cast<const __half2*>(&p2[j]));
        r[2 * j + 0] = (f1.x + f2.x + a[2 * j + 0]) * (1.0f / 3.0f);
        r[2 * j + 1] = (f1.y + f2.y + a[2 * j + 1]) * (1.0f / 3.0f);
    }
    float4* op = reinterpret_cast<float4*>(out + (size_t)row * EMB + sub * 8);
    op[0] = make_float4(r[0], r[1], r[2], r[3]);
    op[1] = make_float4(r[4], r[5], r[6], r[7]);
}

extern "C" void kernel_launch(void* const* d_in, const int* in_sizes, int n_in,
                              void* d_out, int out_size) {
    const float* user = (const float*)d_in[0];
    const float* item = (const float*)d_in[1];
    const void*  arow = d_in[2];
    const void*  acol = d_in[3];
    const float* aval = (const float*)d_in[4];
    float* out = (float*)d_out;

    uint4 *b0, *b1, *b2;
    cudaGetSymbolAddress((void**)&b0, g_b0);
    cudaGetSymbolAddress((void**)&b1, g_b1);
    cudaGetSymbolAddress((void**)&b2, g_b2);

    const int T = 256;
    const int nodeBlocks = (N_NODES + T - 1) / T;
    const int edgeBlocks = (NNZ + T - 1) / T;
    const int embBlocks  = (int)(((size_t)N_NODES * EMB + T - 1) / T);
    const int spmmBlocks = (N_NODES * 8 + T - 1) / T;   // 8 lanes per row

    // ---- build compact CSR (two-pass) ----
    k_zero_detect<<<nodeBlocks, T>>>((const unsigned int*)arow);
    k_hist<<<edgeBlocks, T>>>(arow);
    k_scan_chunks<<<NUM_CHUNKS, SCAN_CHUNK>>>();
    k_scan_bsum<<<1, 256>>>();
    k_finalize_ptr<<<nodeBlocks, T>>>();
    k_scatter<<<edgeBlocks, T>>>(arow, acol, aval);

    // ---- init ego (fp16) ----
    k_init<<<embBlocks, T>>>(user, item);

    // ---- 3 propagation layers; layer 3 fuses the mean reduction ----
    k_spmm_mid <<<spmmBlocks, T>>>(b0, b1);        // e1 = A @ ego0
    k_spmm_mid <<<spmmBlocks, T>>>(b1, b2);        // e2 = A @ e1
    k_spmm_last<<<spmmBlocks, T>>>(b2, b1, out);   // out = (e1+e2+A@e2)/3
}